// round 3
// baseline (speedup 1.0000x reference)
#include <cuda_runtime.h>

#define NEG_INF   (-3.4e38f)
#define NTHREADS  1024
#define FLAG_CAP  16384

// One block per graph segment (batch is sorted -> contiguous rows).
// Pass 1: per-column segment max (float4, fully coalesced).
// Pass 2: warp-per-row equality vs max, walked backward (MRU-first -> L2 hits,
//         since 1 CTA/SM keeps the live working set ~74MB < L2).
// Pass 3: attn = flag / max(count,1)  (bit-exact vs reference).
//
// batch dtype is detected at runtime (int32 vs int64): JAX with x64 disabled
// silently downcasts .astype(int64) to int32, so we must handle both.
__global__ __launch_bounds__(NTHREADS, 1)
void segmax_fused_kernel(const float4* __restrict__ x4,
                         const int* __restrict__ batchw,   // raw 32-bit words
                         float4* __restrict__ emb4,
                         float* __restrict__ attn,
                         int N)
{
    extern __shared__ unsigned char smem[];
    float4* part = (float4*)smem;                               // 1024 * 16B = 16 KB
    float4* mfin = (float4*)(smem + NTHREADS * 16);             // 64 * 16B  =  1 KB
    int*    sh   = (int*)(smem + NTHREADS * 16 + 64 * 16);      // [0]=start [1]=end [2]=count [3]=is64
    unsigned char* flags = smem + NTHREADS * 16 + 64 * 16 + 16; // FLAG_CAP bytes

    const int g   = blockIdx.x;
    const int tid = threadIdx.x;

    // --- dtype detection ---
    // int64 data read as int32 words: word[N-1] (N even) is a high half == 0.
    // int32 data: word[N-1] is the last sorted batch id (nonzero w.p. ~1).
    if (tid == 3) sh[3] = (N >= 2 && batchw[N - 1] == 0) ? 1 : 0;
    if (tid == 2) sh[2] = 0;
    __syncthreads();
    const int is64 = sh[3];

    // --- segment bounds: lower_bound(g), lower_bound(g+1) ---
    if (tid < 2) {
        int key = g + tid;
        int lo = 0, hi = N;
        while (lo < hi) {
            int mid = (lo + hi) >> 1;
            int v = is64 ? batchw[2 * mid] : batchw[mid];  // low word == value (0..G-1)
            if (v < key) lo = mid + 1; else hi = mid;
        }
        sh[tid] = lo;
    }
    __syncthreads();
    const int start = sh[0];
    const int end   = sh[1];
    const int len   = end - start;

    // --- pass 1: segment max per column (D=256 -> 64 float4 columns) ---
    const int q = tid & 63;   // float4 column
    const int s = tid >> 6;   // row subgroup 0..15
    float4 m = make_float4(NEG_INF, NEG_INF, NEG_INF, NEG_INF);
    for (int r = start + s; r < end; r += 16) {
        float4 v = x4[(size_t)r * 64 + q];
        m.x = fmaxf(m.x, v.x); m.y = fmaxf(m.y, v.y);
        m.z = fmaxf(m.z, v.z); m.w = fmaxf(m.w, v.w);
    }
    part[tid] = m;
    __syncthreads();
    if (tid < 64) {
        float4 mm = part[tid];
        #pragma unroll
        for (int k = 1; k < 16; k++) {
            float4 p = part[k * 64 + tid];
            mm.x = fmaxf(mm.x, p.x); mm.y = fmaxf(mm.y, p.y);
            mm.z = fmaxf(mm.z, p.z); mm.w = fmaxf(mm.w, p.w);
        }
        // empty segment: stays NEG_INF == reference's maximum(-inf, NEG_INF)
        mfin[tid] = mm;
        emb4[(size_t)g * 64 + tid] = mm;
    }
    __syncthreads();

    // --- pass 2: warp per row, backward (MRU-first for L2) ---
    const int warp = tid >> 5;
    const int lane = tid & 31;
    const bool useSmemFlags = (len <= FLAG_CAP);
    const float4 ma = mfin[lane];
    const float4 mb = mfin[32 + lane];
    int myCount = 0;
    for (int r = end - 1 - warp; r >= start; r -= 32) {
        float4 a = x4[(size_t)r * 64 + lane];
        float4 b = x4[(size_t)r * 64 + 32 + lane];
        bool hit = (a.x == ma.x) || (a.y == ma.y) || (a.z == ma.z) || (a.w == ma.w)
                || (b.x == mb.x) || (b.y == mb.y) || (b.z == mb.z) || (b.w == mb.w);
        unsigned anyhit = __any_sync(0xffffffffu, hit);
        if (lane == 0) {
            myCount += anyhit ? 1 : 0;
            if (useSmemFlags) flags[r - start] = (unsigned char)(anyhit ? 1 : 0);
            else              attn[r] = anyhit ? 1.0f : 0.0f;   // rare fallback path
        }
    }
    if (lane == 0 && myCount) atomicAdd(&sh[2], myCount);
    __syncthreads();

    // --- pass 3: normalize ---
    const float scale = 1.0f / fmaxf((float)sh[2], 1.0f);
    if (useSmemFlags) {
        for (int i = tid; i < len; i += NTHREADS)
            attn[start + i] = flags[i] ? scale : 0.0f;
    } else {
        for (int i = tid; i < len; i += NTHREADS)
            attn[start + i] *= scale;
    }
}

extern "C" void kernel_launch(void* const* d_in, const int* in_sizes, int n_in,
                              void* d_out, int out_size)
{
    const float* x      = (const float*)d_in[0];
    const int*   batchw = (const int*)d_in[1];   // raw words; dtype detected in-kernel

    const int N = in_sizes[1];                 // 1048576 nodes
    const int D = in_sizes[0] / N;             // 256 features
    int G = (out_size - N) / D;                // 2048 graphs (layout: [emb | attn])
    if (G < 1) G = 1;                          // defensive; never expected

    float* emb  = (float*)d_out;
    float* attn = emb + (size_t)G * D;

    // Static smem need is ~17.5 KB; request ~200KB to force 1 CTA/SM so each
    // segment stays L2-resident between pass 1 and pass 2. Degrade gracefully.
    static_assert(NTHREADS * 16 + 64 * 16 + 16 + FLAG_CAP <= 48 * 1024, "base smem");
    size_t smem_req = 200 * 1024;
    if (cudaFuncSetAttribute(segmax_fused_kernel,
                             cudaFuncAttributeMaxDynamicSharedMemorySize,
                             (int)smem_req) != cudaSuccess) {
        smem_req = 100 * 1024;
        if (cudaFuncSetAttribute(segmax_fused_kernel,
                                 cudaFuncAttributeMaxDynamicSharedMemorySize,
                                 (int)smem_req) != cudaSuccess) {
            smem_req = NTHREADS * 16 + 64 * 16 + 16 + FLAG_CAP;  // minimum needed
        }
    }

    segmax_fused_kernel<<<G, NTHREADS, smem_req>>>(
        (const float4*)x, batchw, (float4*)emb, attn, N);
}

// round 4
// speedup vs baseline: 1.1121x; 1.1121x over previous
#include <cuda_runtime.h>

#define NEG_INF   (-3.4e38f)
#define NTHREADS  1024
#define FLAG_CAP  16384

__device__ __forceinline__ float4 f4max(float4 a, float4 b) {
    return make_float4(fmaxf(a.x,b.x), fmaxf(a.y,b.y), fmaxf(a.z,b.z), fmaxf(a.w,b.w));
}
__device__ __forceinline__ bool f4hit(float4 a, float4 m) {
    return (a.x==m.x) | (a.y==m.y) | (a.z==m.z) | (a.w==m.w);
}

// One block per graph segment (batch sorted -> contiguous rows).
// Pass 1: per-column segment max, unrolled x4 for MLP.
// Pass 2: warp-per-row equality vs max, unrolled x4, __ldcs (lines are dead after use).
// Pass 3: attn = flag / max(count,1)   (bit-exact vs reference).
__global__ __launch_bounds__(NTHREADS, 1)
void segmax_fused_kernel(const float4* __restrict__ x4,
                         const int* __restrict__ batchw,   // raw 32-bit words
                         float4* __restrict__ emb4,
                         float* __restrict__ attn,
                         int N)
{
    extern __shared__ unsigned char smem[];
    float4* part = (float4*)smem;                               // 1024*16B = 16 KB
    float4* mfin = (float4*)(smem + NTHREADS * 16);             // 64*16B  =  1 KB
    int*    sh   = (int*)(smem + NTHREADS * 16 + 64 * 16);      // [0]=start [1]=end [2]=count [3]=is64
    unsigned char* flags = smem + NTHREADS * 16 + 64 * 16 + 16; // FLAG_CAP bytes

    const int g   = blockIdx.x;
    const int tid = threadIdx.x;

    // dtype detect: int64 read as 32-bit words -> word[N-1] is a high half == 0.
    if (tid == 3) sh[3] = (N >= 2 && batchw[N - 1] == 0) ? 1 : 0;
    if (tid == 2) sh[2] = 0;
    __syncthreads();
    const int is64 = sh[3];

    // segment bounds: lower_bound(g), lower_bound(g+1)
    if (tid < 2) {
        int key = g + tid;
        int lo = 0, hi = N;
        while (lo < hi) {
            int mid = (lo + hi) >> 1;
            int v = is64 ? batchw[2 * mid] : batchw[mid];
            if (v < key) lo = mid + 1; else hi = mid;
        }
        sh[tid] = lo;
    }
    __syncthreads();
    const int start = sh[0];
    const int end   = sh[1];
    const int len   = end - start;

    // --- pass 1: segment max per column (64 float4 columns), unroll x4 ---
    {
        const int q = tid & 63;   // float4 column
        const int s = tid >> 6;   // row subgroup 0..15
        float4 m0 = make_float4(NEG_INF, NEG_INF, NEG_INF, NEG_INF);
        float4 m1 = m0;
        int r = start + s;
        for (; r + 48 < end; r += 64) {
            float4 v0 = x4[(size_t)(r     ) * 64 + q];
            float4 v1 = x4[(size_t)(r + 16) * 64 + q];
            float4 v2 = x4[(size_t)(r + 32) * 64 + q];
            float4 v3 = x4[(size_t)(r + 48) * 64 + q];
            m0 = f4max(m0, f4max(v0, v2));
            m1 = f4max(m1, f4max(v1, v3));
        }
        for (; r < end; r += 16)
            m0 = f4max(m0, x4[(size_t)r * 64 + q]);
        part[tid] = f4max(m0, m1);
    }
    __syncthreads();
    if (tid < 64) {
        float4 mm = part[tid];
        #pragma unroll
        for (int k = 1; k < 16; k++)
            mm = f4max(mm, part[k * 64 + tid]);
        mfin[tid] = mm;                       // empty segment stays NEG_INF (== ref)
        emb4[(size_t)g * 64 + tid] = mm;
    }
    __syncthreads();

    // --- pass 2: warp per row, backward, unroll x4, streaming loads ---
    const int warp = tid >> 5;
    const int lane = tid & 31;
    const bool useSmemFlags = (len <= FLAG_CAP);
    const float4 ma = mfin[lane];
    const float4 mb = mfin[32 + lane];
    int myCount = 0;
    int r = end - 1 - warp;
    for (; r - 96 >= start; r -= 128) {
        const float4* p0 = &x4[(size_t)(r     ) * 64 + lane];
        const float4* p1 = &x4[(size_t)(r - 32) * 64 + lane];
        const float4* p2 = &x4[(size_t)(r - 64) * 64 + lane];
        const float4* p3 = &x4[(size_t)(r - 96) * 64 + lane];
        float4 a0 = __ldcs(p0), b0 = __ldcs(p0 + 32);
        float4 a1 = __ldcs(p1), b1 = __ldcs(p1 + 32);
        float4 a2 = __ldcs(p2), b2 = __ldcs(p2 + 32);
        float4 a3 = __ldcs(p3), b3 = __ldcs(p3 + 32);
        unsigned h0 = __any_sync(0xffffffffu, f4hit(a0, ma) | f4hit(b0, mb));
        unsigned h1 = __any_sync(0xffffffffu, f4hit(a1, ma) | f4hit(b1, mb));
        unsigned h2 = __any_sync(0xffffffffu, f4hit(a2, ma) | f4hit(b2, mb));
        unsigned h3 = __any_sync(0xffffffffu, f4hit(a3, ma) | f4hit(b3, mb));
        if (lane == 0) {
            myCount += (h0?1:0) + (h1?1:0) + (h2?1:0) + (h3?1:0);
            if (useSmemFlags) {
                flags[r      - start] = (unsigned char)(h0?1:0);
                flags[r - 32 - start] = (unsigned char)(h1?1:0);
                flags[r - 64 - start] = (unsigned char)(h2?1:0);
                flags[r - 96 - start] = (unsigned char)(h3?1:0);
            } else {
                attn[r     ] = h0 ? 1.0f : 0.0f;
                attn[r - 32] = h1 ? 1.0f : 0.0f;
                attn[r - 64] = h2 ? 1.0f : 0.0f;
                attn[r - 96] = h3 ? 1.0f : 0.0f;
            }
        }
    }
    for (; r >= start; r -= 32) {
        const float4* p = &x4[(size_t)r * 64 + lane];
        float4 a = __ldcs(p), b = __ldcs(p + 32);
        unsigned h = __any_sync(0xffffffffu, f4hit(a, ma) | f4hit(b, mb));
        if (lane == 0) {
            myCount += h ? 1 : 0;
            if (useSmemFlags) flags[r - start] = (unsigned char)(h?1:0);
            else              attn[r] = h ? 1.0f : 0.0f;
        }
    }
    if (lane == 0 && myCount) atomicAdd(&sh[2], myCount);
    __syncthreads();

    // --- pass 3: normalize ---
    const float scale = 1.0f / fmaxf((float)sh[2], 1.0f);
    if (useSmemFlags) {
        for (int i = tid; i < len; i += NTHREADS)
            attn[start + i] = flags[i] ? scale : 0.0f;
    } else {
        for (int i = tid; i < len; i += NTHREADS)
            attn[start + i] *= scale;
    }
}

extern "C" void kernel_launch(void* const* d_in, const int* in_sizes, int n_in,
                              void* d_out, int out_size)
{
    const float* x      = (const float*)d_in[0];
    const int*   batchw = (const int*)d_in[1];

    const int N = in_sizes[1];
    const int D = in_sizes[0] / N;
    int G = (out_size - N) / D;                // layout: [emb (G*D) | attn (N)]
    if (G < 1) G = 1;

    float* emb  = (float*)d_out;
    float* attn = emb + (size_t)G * D;

    // Request ~200KB dynamic smem -> 1 CTA/SM -> concurrent working set
    // (148 segments x ~512KB) stays L2-resident between pass 1 and pass 2.
    static_assert(NTHREADS * 16 + 64 * 16 + 16 + FLAG_CAP <= 48 * 1024, "base smem");
    size_t smem_req = 200 * 1024;
    if (cudaFuncSetAttribute(segmax_fused_kernel,
                             cudaFuncAttributeMaxDynamicSharedMemorySize,
                             (int)smem_req) != cudaSuccess) {
        smem_req = 100 * 1024;
        if (cudaFuncSetAttribute(segmax_fused_kernel,
                                 cudaFuncAttributeMaxDynamicSharedMemorySize,
                                 (int)smem_req) != cudaSuccess) {
            smem_req = NTHREADS * 16 + 64 * 16 + 16 + FLAG_CAP;
        }
    }

    segmax_fused_kernel<<<G, NTHREADS, smem_req>>>(
        (const float4*)x, batchw, (float4*)emb, attn, N);
}

// round 6
// speedup vs baseline: 1.2737x; 1.1453x over previous
#include <cuda_runtime.h>

#define NEG_INF   (-3.4e38f)
#define NTHREADS  1024
#define HALF      512
#define FLAG_CAP  4096        // per pipeline buffer

// named barriers (id 0 is __syncthreads)
#define BAR_FULL0   1         // +b : producer arrives, consumer syncs
#define BAR_EMPTY0  3         // +b : consumer arrives, producer syncs
#define BAR_PINT    5         // producer-internal (512)
#define BAR_CINT    6         // consumer-internal (512)

__device__ __forceinline__ void bar_sync(int id, int cnt) {
    asm volatile("bar.sync %0, %1;" :: "r"(id), "r"(cnt) : "memory");
}
__device__ __forceinline__ void bar_arrive(int id, int cnt) {
    asm volatile("bar.arrive %0, %1;" :: "r"(id), "r"(cnt) : "memory");
}
__device__ __forceinline__ float4 f4max(float4 a, float4 b) {
    return make_float4(fmaxf(a.x,b.x), fmaxf(a.y,b.y), fmaxf(a.z,b.z), fmaxf(a.w,b.w));
}
__device__ __forceinline__ bool f4hit(float4 a, float4 m) {
    return (a.x==m.x) | (a.y==m.y) | (a.z==m.z) | (a.w==m.w);
}

// Persistent, warp-specialized pipeline. Producer warps stream segment i+1 from
// DRAM computing the per-column max; consumer warps re-read segment i from L2
// doing the equality test + normalization. Double-buffered smem handoff.
__global__ __launch_bounds__(NTHREADS, 1)
void segmax_pipe_kernel(const float4* __restrict__ x4,
                        const int* __restrict__ batchw,   // raw 32-bit words
                        float4* __restrict__ emb4,
                        float* __restrict__ attn,
                        int N, int NSEG)
{
    extern __shared__ unsigned char smem[];
    float4* part = (float4*)smem;                       // 512 * 16 = 8192 B (producer scratch)
    float4* mfin = (float4*)(smem + 8192);              // 2 * 64 * 16 = 2048 B
    int*    meta = (int*)(smem + 8192 + 2048);          // 2 * {start,end,cnt,pad}
    int*    misc = (int*)(smem + 8192 + 2048 + 32);     // [0] = is64
    unsigned char* flags = smem + 8192 + 2048 + 48;     // 2 * FLAG_CAP

    const int tid = threadIdx.x;

    // dtype detect: int64 viewed as 32-bit words -> word[N-1] is a high half == 0.
    if (tid == 0) misc[0] = (N >= 2 && batchw[N - 1] == 0) ? 1 : 0;
    __syncthreads();                                    // only block-wide sync; groups diverge after
    const int is64 = misc[0];

    if (tid >= HALF) {
        // ---------------- producer: pass 1 (segment max) ----------------
        const int ptid = tid - HALF;
        const int q = ptid & 63;        // float4 column
        const int s = ptid >> 6;        // row subgroup 0..7
        int it = 0;
        for (int seg = blockIdx.x; seg < NSEG; seg += gridDim.x, it++) {
            const int b = it & 1;
            if (it >= 2) bar_sync(BAR_EMPTY0 + b, NTHREADS);   // buffer b free again
            if (ptid < 2) {                                    // lower_bound(seg), lower_bound(seg+1)
                int key = seg + ptid;
                int lo = 0, hi = N;
                while (lo < hi) {
                    int mid = (lo + hi) >> 1;
                    int v = is64 ? batchw[2 * mid] : batchw[mid];
                    if (v < key) lo = mid + 1; else hi = mid;
                }
                meta[b * 4 + ptid] = lo;
            }
            if (ptid == 2) meta[b * 4 + 2] = 0;                // reset count
            bar_sync(BAR_PINT, HALF);
            const int start = meta[b * 4 + 0];
            const int end   = meta[b * 4 + 1];

            float4 m0 = make_float4(NEG_INF, NEG_INF, NEG_INF, NEG_INF);
            float4 m1 = m0;
            int r = start + s;
            for (; r + 24 < end; r += 32) {                    // unroll x4 (stride 8 rows)
                float4 v0 = x4[(size_t)(r     ) * 64 + q];
                float4 v1 = x4[(size_t)(r +  8) * 64 + q];
                float4 v2 = x4[(size_t)(r + 16) * 64 + q];
                float4 v3 = x4[(size_t)(r + 24) * 64 + q];
                m0 = f4max(m0, f4max(v0, v2));
                m1 = f4max(m1, f4max(v1, v3));
            }
            for (; r < end; r += 8)
                m0 = f4max(m0, x4[(size_t)r * 64 + q]);
            part[ptid] = f4max(m0, m1);
            bar_sync(BAR_PINT, HALF);
            if (ptid < 64) {
                float4 mm = part[ptid];
                #pragma unroll
                for (int k = 1; k < 8; k++)
                    mm = f4max(mm, part[k * 64 + ptid]);
                mfin[b * 64 + ptid] = mm;                      // empty seg stays NEG_INF (== ref)
                emb4[(size_t)seg * 64 + ptid] = mm;
            }
            bar_arrive(BAR_FULL0 + b, NTHREADS);               // publish buffer b
        }
    } else {
        // ---------------- consumer: pass 2 (match) + pass 3 (normalize) ----------------
        const int warp = tid >> 5;      // 0..15
        const int lane = tid & 31;
        int it = 0;
        for (int seg = blockIdx.x; seg < NSEG; seg += gridDim.x, it++) {
            const int b = it & 1;
            bar_sync(BAR_FULL0 + b, NTHREADS);                 // wait for max of seg
            const int start = meta[b * 4 + 0];
            const int end   = meta[b * 4 + 1];
            const int len   = end - start;
            const float4 ma = mfin[b * 64 + lane];
            const float4 mb = mfin[b * 64 + 32 + lane];
            unsigned char* flg = flags + b * FLAG_CAP;
            const bool useS = (len <= FLAG_CAP);

            int myCount = 0;
            int r = end - 1 - warp;                            // backward = MRU-first in L2
            for (; r - 48 >= start; r -= 64) {                 // unroll x4 (stride 16 rows)
                const float4* p0 = &x4[(size_t)(r     ) * 64 + lane];
                const float4* p1 = &x4[(size_t)(r - 16) * 64 + lane];
                const float4* p2 = &x4[(size_t)(r - 32) * 64 + lane];
                const float4* p3 = &x4[(size_t)(r - 48) * 64 + lane];
                float4 a0 = __ldcs(p0), b0 = __ldcs(p0 + 32);  // dead after use: evict-first
                float4 a1 = __ldcs(p1), b1 = __ldcs(p1 + 32);
                float4 a2 = __ldcs(p2), b2 = __ldcs(p2 + 32);
                float4 a3 = __ldcs(p3), b3 = __ldcs(p3 + 32);
                unsigned h0 = __any_sync(0xffffffffu, f4hit(a0, ma) | f4hit(b0, mb));
                unsigned h1 = __any_sync(0xffffffffu, f4hit(a1, ma) | f4hit(b1, mb));
                unsigned h2 = __any_sync(0xffffffffu, f4hit(a2, ma) | f4hit(b2, mb));
                unsigned h3 = __any_sync(0xffffffffu, f4hit(a3, ma) | f4hit(b3, mb));
                if (lane == 0) {
                    myCount += (h0?1:0) + (h1?1:0) + (h2?1:0) + (h3?1:0);
                    if (useS) {
                        flg[r      - start] = (unsigned char)(h0?1:0);
                        flg[r - 16 - start] = (unsigned char)(h1?1:0);
                        flg[r - 32 - start] = (unsigned char)(h2?1:0);
                        flg[r - 48 - start] = (unsigned char)(h3?1:0);
                    } else {
                        attn[r     ] = h0 ? 1.0f : 0.0f;
                        attn[r - 16] = h1 ? 1.0f : 0.0f;
                        attn[r - 32] = h2 ? 1.0f : 0.0f;
                        attn[r - 48] = h3 ? 1.0f : 0.0f;
                    }
                }
            }
            for (; r >= start; r -= 16) {
                const float4* p = &x4[(size_t)r * 64 + lane];
                float4 a = __ldcs(p), bb = __ldcs(p + 32);
                unsigned h = __any_sync(0xffffffffu, f4hit(a, ma) | f4hit(bb, mb));
                if (lane == 0) {
                    myCount += h ? 1 : 0;
                    if (useS) flg[r - start] = (unsigned char)(h?1:0);
                    else      attn[r] = h ? 1.0f : 0.0f;
                }
            }
            if (lane == 0 && myCount) atomicAdd(&meta[b * 4 + 2], myCount);
            bar_sync(BAR_CINT, HALF);                          // count complete
            const float scale = 1.0f / fmaxf((float)meta[b * 4 + 2], 1.0f);
            if (useS) {
                for (int i = tid; i < len; i += HALF)
                    attn[start + i] = flg[i] ? scale : 0.0f;
            } else {
                for (int i = tid; i < len; i += HALF)
                    attn[start + i] *= scale;
            }
            bar_arrive(BAR_EMPTY0 + b, NTHREADS);              // release buffer b
        }
    }
}

extern "C" void kernel_launch(void* const* d_in, const int* in_sizes, int n_in,
                              void* d_out, int out_size)
{
    const float* x      = (const float*)d_in[0];
    const int*   batchw = (const int*)d_in[1];

    const int N = in_sizes[1];
    const int D = in_sizes[0] / N;
    int G = (out_size - N) / D;                // layout: [emb (G*D) | attn (N)]
    if (G < 1) G = 1;

    float* emb  = (float*)d_out;
    float* attn = emb + (size_t)G * D;

    int nsm = 148;
    cudaDeviceGetAttribute(&nsm, cudaDevAttrMultiProcessorCount, 0);
    int grid = (G < nsm) ? G : nsm;

    // ~18.5KB needed; request ~200KB to force 1 CTA/SM so the pipeline's live
    // working set (2 segments/SM) stays L2-resident. Degrade gracefully.
    size_t base = 8192 + 2048 + 48 + 2 * FLAG_CAP;
    size_t smem_req = 200 * 1024;
    if (cudaFuncSetAttribute(segmax_pipe_kernel,
                             cudaFuncAttributeMaxDynamicSharedMemorySize,
                             (int)smem_req) != cudaSuccess) {
        smem_req = 100 * 1024;
        if (cudaFuncSetAttribute(segmax_pipe_kernel,
                                 cudaFuncAttributeMaxDynamicSharedMemorySize,
                                 (int)smem_req) != cudaSuccess) {
            smem_req = base;
        }
    }

    segmax_pipe_kernel<<<grid, NTHREADS, smem_req>>>(
        (const float4*)x, batchw, (float4*)emb, attn, N, G);
}

// round 7
// speedup vs baseline: 1.4863x; 1.1669x over previous
#include <cuda_runtime.h>

#define NEG_INF   (-3.4e38f)
#define NT        512
#define FLAG_CAP  8192

__device__ __forceinline__ void upd(float v, int r, float& m, int& idx, int& tie) {
    if (v > m)       { m = v; idx = r; tie = 0; }
    else if (v == m) { tie = 1; }
}
// combine b into a (per scalar column). Empty entries have idx < 0.
__device__ __forceinline__ void comb(float& am, int& ai, int& at,
                                     float bm, int bi, int bt) {
    if (bm > am || (bm == am && ai < 0)) { am = bm; ai = bi; at = bt; }
    else if (bm == am && bi >= 0)        { at = 1; }
}
__device__ __forceinline__ bool f4hit(float4 a, float4 m) {
    return (a.x==m.x) | (a.y==m.y) | (a.z==m.z) | (a.w==m.w);
}

// One block per segment, single streaming pass.
// Tracks (max, argmax, tie) per scalar column; matching rows = argmax rows
// unless a tie-at-max exists (rare) -> exact fallback rescan of the segment.
__global__ __launch_bounds__(NT)
void segmax_argmax_kernel(const float4* __restrict__ x4,
                          const int* __restrict__ batchw,   // raw 32-bit words
                          float4* __restrict__ emb4,
                          float* __restrict__ attn,
                          int N)
{
    extern __shared__ unsigned char smem[];
    float4* partM = (float4*)smem;                          //  8192 B
    int4*   partI = (int4*)(smem + 8192);                   //  8192 B
    int*    partT = (int*)(smem + 16384);                   //  2048 B (4 tie bits/thread)
    float4* mfin  = (float4*)(smem + 18432);                //  1024 B
    int*    sh    = (int*)(smem + 19456);                   //    32 B: 0=start 1=end 2=cnt 3=tie 4=is64
    unsigned char* flags = smem + 19488;                    //  FLAG_CAP B

    const int g   = blockIdx.x;
    const int tid = threadIdx.x;

    if (tid == 2) sh[2] = 0;
    if (tid == 3) sh[3] = 0;
    // dtype detect: int64 viewed as 32-bit words -> word[N-1] is a high half == 0.
    if (tid == 4) sh[4] = (N >= 2 && batchw[N - 1] == 0) ? 1 : 0;
    for (int i = tid; i < FLAG_CAP / 4; i += NT) ((int*)flags)[i] = 0;
    __syncthreads();
    const int is64 = sh[4];

    if (tid < 2) {                        // lower_bound(g), lower_bound(g+1)
        int key = g + tid;
        int lo = 0, hi = N;
        while (lo < hi) {
            int mid = (lo + hi) >> 1;
            int v = is64 ? batchw[2 * mid] : batchw[mid];
            if (v < key) lo = mid + 1; else hi = mid;
        }
        sh[tid] = lo;
    }
    __syncthreads();
    const int start = sh[0];
    const int end   = sh[1];
    const int len   = end - start;

    // --- streaming pass: (max, argmax, tie) per scalar column ---
    {
        const int q = tid & 63;           // float4 column
        const int s = tid >> 6;           // row subgroup 0..7
        float mx = NEG_INF, my = NEG_INF, mz = NEG_INF, mw = NEG_INF;
        int   ix = -1, iy = -1, iz = -1, iw = -1;
        int   tx = 0,  ty = 0,  tz = 0,  tw = 0;
        int r = start + s;
        for (; r + 24 < end; r += 32) {   // unroll x4, stride 8 rows
            float4 v0 = x4[(size_t)(r     ) * 64 + q];
            float4 v1 = x4[(size_t)(r +  8) * 64 + q];
            float4 v2 = x4[(size_t)(r + 16) * 64 + q];
            float4 v3 = x4[(size_t)(r + 24) * 64 + q];
            upd(v0.x, r,      mx, ix, tx); upd(v0.y, r,      my, iy, ty);
            upd(v0.z, r,      mz, iz, tz); upd(v0.w, r,      mw, iw, tw);
            upd(v1.x, r + 8,  mx, ix, tx); upd(v1.y, r + 8,  my, iy, ty);
            upd(v1.z, r + 8,  mz, iz, tz); upd(v1.w, r + 8,  mw, iw, tw);
            upd(v2.x, r + 16, mx, ix, tx); upd(v2.y, r + 16, my, iy, ty);
            upd(v2.z, r + 16, mz, iz, tz); upd(v2.w, r + 16, mw, iw, tw);
            upd(v3.x, r + 24, mx, ix, tx); upd(v3.y, r + 24, my, iy, ty);
            upd(v3.z, r + 24, mz, iz, tz); upd(v3.w, r + 24, mw, iw, tw);
        }
        for (; r < end; r += 8) {
            float4 v = x4[(size_t)r * 64 + q];
            upd(v.x, r, mx, ix, tx); upd(v.y, r, my, iy, ty);
            upd(v.z, r, mz, iz, tz); upd(v.w, r, mw, iw, tw);
        }
        partM[tid] = make_float4(mx, my, mz, mw);
        partI[tid] = make_int4(ix, iy, iz, iw);
        partT[tid] = tx | (ty << 1) | (tz << 2) | (tw << 3);
    }
    __syncthreads();

    // --- reduce 8 subgroups; emit emb, flags, tie ---
    if (tid < 64) {
        float4 m = partM[tid]; int4 idx = partI[tid]; int tb = partT[tid];
        int ax = tb & 1, ay = (tb >> 1) & 1, az = (tb >> 2) & 1, aw = (tb >> 3) & 1;
        #pragma unroll
        for (int k = 1; k < 8; k++) {
            float4 bm = partM[k * 64 + tid];
            int4   bi = partI[k * 64 + tid];
            int    bt = partT[k * 64 + tid];
            comb(m.x, idx.x, ax, bm.x, bi.x,  bt       & 1);
            comb(m.y, idx.y, ay, bm.y, bi.y, (bt >> 1) & 1);
            comb(m.z, idx.z, az, bm.z, bi.z, (bt >> 2) & 1);
            comb(m.w, idx.w, aw, bm.w, bi.w, (bt >> 3) & 1);
        }
        mfin[tid] = m;                         // empty segment stays NEG_INF (== ref)
        emb4[(size_t)g * 64 + tid] = m;
        if (len <= FLAG_CAP) {
            if (idx.x >= 0) flags[idx.x - start] = 1;
            if (idx.y >= 0) flags[idx.y - start] = 1;
            if (idx.z >= 0) flags[idx.z - start] = 1;
            if (idx.w >= 0) flags[idx.w - start] = 1;
        }
        if (ax | ay | az | aw) sh[3] = 1;      // benign race: all write 1
    }
    __syncthreads();

    const int  tie   = sh[3];
    const bool small = (len <= FLAG_CAP);
    const int  warp  = tid >> 5;
    const int  lane  = tid & 31;

    if (!tie && small) {
        // count flagged rows (bytes are 0/1; word*0x01010101>>24 = byte sum)
        unsigned local = 0;
        for (int i = tid; i < (len + 3) / 4; i += NT) {
            unsigned w = ((unsigned*)flags)[i];
            local += (w * 0x01010101u) >> 24;
        }
        #pragma unroll
        for (int o = 16; o; o >>= 1) local += __shfl_down_sync(0xffffffffu, local, o);
        if (lane == 0 && local) atomicAdd(&sh[2], (int)local);
        __syncthreads();
        const float scale = 1.0f / fmaxf((float)sh[2], 1.0f);
        for (int i = tid; i < len; i += NT)
            attn[start + i] = flags[i] ? scale : 0.0f;
    } else {
        // rare: tie at a column max, or oversized segment -> exact rescan
        if (small) { for (int i = tid; i < FLAG_CAP / 4; i += NT) ((int*)flags)[i] = 0; }
        __syncthreads();
        const float4 ma = mfin[lane];
        const float4 mb = mfin[32 + lane];
        int myCount = 0;
        for (int r = end - 1 - warp; r >= start; r -= 16) {
            float4 a = x4[(size_t)r * 64 + lane];
            float4 b = x4[(size_t)r * 64 + 32 + lane];
            unsigned h = __any_sync(0xffffffffu, f4hit(a, ma) | f4hit(b, mb));
            if (lane == 0) {
                myCount += h ? 1 : 0;
                if (small) flags[r - start] = (unsigned char)(h ? 1 : 0);
                else       attn[r] = h ? 1.0f : 0.0f;
            }
        }
        if (lane == 0 && myCount) atomicAdd(&sh[2], myCount);
        __syncthreads();
        const float scale = 1.0f / fmaxf((float)sh[2], 1.0f);
        if (small) {
            for (int i = tid; i < len; i += NT)
                attn[start + i] = flags[i] ? scale : 0.0f;
        } else {
            for (int i = tid; i < len; i += NT)
                attn[start + i] *= scale;
        }
    }
}

extern "C" void kernel_launch(void* const* d_in, const int* in_sizes, int n_in,
                              void* d_out, int out_size)
{
    const float* x      = (const float*)d_in[0];
    const int*   batchw = (const int*)d_in[1];

    const int N = in_sizes[1];
    const int D = in_sizes[0] / N;
    int G = (out_size - N) / D;                // layout: [emb (G*D) | attn (N)]
    if (G < 1) G = 1;

    float* emb  = (float*)d_out;
    float* attn = emb + (size_t)G * D;

    const size_t smem = 19488 + FLAG_CAP;      // ~27 KB -> multi-CTA/SM occupancy
    segmax_argmax_kernel<<<G, NT, smem>>>(
        (const float4*)x, batchw, (float4*)emb, attn, N);
}

// round 8
// speedup vs baseline: 1.7147x; 1.1537x over previous
#include <cuda_runtime.h>

#define NEG_INF   (-3.4e38f)
#define NT        256
#define FLAG_CAP  8192

__device__ __forceinline__ void upd(float v, int r, float& m, int& idx, int& tie) {
    if (v > m)       { m = v; idx = r; tie = 0; }
    else if (v == m) { tie = 1; }
}
// combine b into a (per scalar column). Empty entries have idx < 0.
__device__ __forceinline__ void comb(float& am, int& ai, int& at,
                                     float bm, int bi, int bt) {
    if (bm > am || (bm == am && ai < 0)) { am = bm; ai = bi; at = bt; }
    else if (bm == am && bi >= 0)        { at = 1; }
}
__device__ __forceinline__ bool f4hit(float4 a, float4 m) {
    return (a.x==m.x) | (a.y==m.y) | (a.z==m.z) | (a.w==m.w);
}

// One block per segment, single streaming pass with (max, argmax, tie) per
// scalar column. Hot loop: 8-row fmax tree + one compare per column; the exact
// argmax/tie update runs only when the 8-row block max reaches the running max
// (expected ~ln(len/8) times per thread). Ties at max -> exact rescan fallback.
__global__ __launch_bounds__(NT)
void segmax_argmax_kernel(const float4* __restrict__ x4,
                          const int* __restrict__ batchw,   // raw 32-bit words
                          float4* __restrict__ emb4,
                          float* __restrict__ attn,
                          int N)
{
    extern __shared__ unsigned char smem[];
    float4* partM = (float4*)smem;                          // NT*16 = 4096 B
    int4*   partI = (int4*)(smem + 4096);                   // 4096 B
    int*    partT = (int*)(smem + 8192);                    // 1024 B
    float4* mfin  = (float4*)(smem + 9216);                 // 1024 B
    int*    sh    = (int*)(smem + 10240);                   //   32 B: 0=start 1=end 2=cnt 3=tie 4=is64
    unsigned char* flags = smem + 10272;                    // FLAG_CAP B

    const int g   = blockIdx.x;
    const int tid = threadIdx.x;

    if (tid == 2) sh[2] = 0;
    if (tid == 3) sh[3] = 0;
    // dtype detect: int64 viewed as 32-bit words -> word[N-1] is a high half == 0.
    if (tid == 4) sh[4] = (N >= 2 && batchw[N - 1] == 0) ? 1 : 0;
    for (int i = tid; i < FLAG_CAP / 4; i += NT) ((int*)flags)[i] = 0;
    __syncthreads();
    const int is64 = sh[4];

    if (tid < 2) {                        // lower_bound(g), lower_bound(g+1)
        int key = g + tid;
        int lo = 0, hi = N;
        while (lo < hi) {
            int mid = (lo + hi) >> 1;
            int v = is64 ? batchw[2 * mid] : batchw[mid];
            if (v < key) lo = mid + 1; else hi = mid;
        }
        sh[tid] = lo;
    }
    __syncthreads();
    const int start = sh[0];
    const int end   = sh[1];
    const int len   = end - start;

    // --- streaming pass ---
    {
        const int q = tid & 63;           // float4 column group
        const int s = tid >> 6;           // row subgroup 0..3
        float mx = NEG_INF, my = NEG_INF, mz = NEG_INF, mw = NEG_INF;
        int   ix = -1, iy = -1, iz = -1, iw = -1;
        int   tx = 0,  ty = 0,  tz = 0,  tw = 0;
        int r = start + s;
        for (; r + 28 < end; r += 32) {   // 8 rows/iter, stride 4
            float4 v0 = __ldcs(&x4[(size_t)(r     ) * 64 + q]);
            float4 v1 = __ldcs(&x4[(size_t)(r +  4) * 64 + q]);
            float4 v2 = __ldcs(&x4[(size_t)(r +  8) * 64 + q]);
            float4 v3 = __ldcs(&x4[(size_t)(r + 12) * 64 + q]);
            float4 v4 = __ldcs(&x4[(size_t)(r + 16) * 64 + q]);
            float4 v5 = __ldcs(&x4[(size_t)(r + 20) * 64 + q]);
            float4 v6 = __ldcs(&x4[(size_t)(r + 24) * 64 + q]);
            float4 v7 = __ldcs(&x4[(size_t)(r + 28) * 64 + q]);
            float cx = fmaxf(fmaxf(fmaxf(v0.x,v1.x), fmaxf(v2.x,v3.x)),
                             fmaxf(fmaxf(v4.x,v5.x), fmaxf(v6.x,v7.x)));
            float cy = fmaxf(fmaxf(fmaxf(v0.y,v1.y), fmaxf(v2.y,v3.y)),
                             fmaxf(fmaxf(v4.y,v5.y), fmaxf(v6.y,v7.y)));
            float cz = fmaxf(fmaxf(fmaxf(v0.z,v1.z), fmaxf(v2.z,v3.z)),
                             fmaxf(fmaxf(v4.z,v5.z), fmaxf(v6.z,v7.z)));
            float cw = fmaxf(fmaxf(fmaxf(v0.w,v1.w), fmaxf(v2.w,v3.w)),
                             fmaxf(fmaxf(v4.w,v5.w), fmaxf(v6.w,v7.w)));
            if (cx >= mx) {               // rare: exact update in row order
                upd(v0.x, r,    mx, ix, tx); upd(v1.x, r+4,  mx, ix, tx);
                upd(v2.x, r+8,  mx, ix, tx); upd(v3.x, r+12, mx, ix, tx);
                upd(v4.x, r+16, mx, ix, tx); upd(v5.x, r+20, mx, ix, tx);
                upd(v6.x, r+24, mx, ix, tx); upd(v7.x, r+28, mx, ix, tx);
            }
            if (cy >= my) {
                upd(v0.y, r,    my, iy, ty); upd(v1.y, r+4,  my, iy, ty);
                upd(v2.y, r+8,  my, iy, ty); upd(v3.y, r+12, my, iy, ty);
                upd(v4.y, r+16, my, iy, ty); upd(v5.y, r+20, my, iy, ty);
                upd(v6.y, r+24, my, iy, ty); upd(v7.y, r+28, my, iy, ty);
            }
            if (cz >= mz) {
                upd(v0.z, r,    mz, iz, tz); upd(v1.z, r+4,  mz, iz, tz);
                upd(v2.z, r+8,  mz, iz, tz); upd(v3.z, r+12, mz, iz, tz);
                upd(v4.z, r+16, mz, iz, tz); upd(v5.z, r+20, mz, iz, tz);
                upd(v6.z, r+24, mz, iz, tz); upd(v7.z, r+28, mz, iz, tz);
            }
            if (cw >= mw) {
                upd(v0.w, r,    mw, iw, tw); upd(v1.w, r+4,  mw, iw, tw);
                upd(v2.w, r+8,  mw, iw, tw); upd(v3.w, r+12, mw, iw, tw);
                upd(v4.w, r+16, mw, iw, tw); upd(v5.w, r+20, mw, iw, tw);
                upd(v6.w, r+24, mw, iw, tw); upd(v7.w, r+28, mw, iw, tw);
            }
        }
        for (; r < end; r += 4) {
            float4 v = __ldcs(&x4[(size_t)r * 64 + q]);
            upd(v.x, r, mx, ix, tx); upd(v.y, r, my, iy, ty);
            upd(v.z, r, mz, iz, tz); upd(v.w, r, mw, iw, tw);
        }
        partM[tid] = make_float4(mx, my, mz, mw);
        partI[tid] = make_int4(ix, iy, iz, iw);
        partT[tid] = tx | (ty << 1) | (tz << 2) | (tw << 3);
    }
    __syncthreads();

    // --- reduce 4 subgroups; emit emb, flags, tie ---
    if (tid < 64) {
        float4 m = partM[tid]; int4 idx = partI[tid]; int tb = partT[tid];
        int ax = tb & 1, ay = (tb >> 1) & 1, az = (tb >> 2) & 1, aw = (tb >> 3) & 1;
        #pragma unroll
        for (int k = 1; k < 4; k++) {
            float4 bm = partM[k * 64 + tid];
            int4   bi = partI[k * 64 + tid];
            int    bt = partT[k * 64 + tid];
            comb(m.x, idx.x, ax, bm.x, bi.x,  bt       & 1);
            comb(m.y, idx.y, ay, bm.y, bi.y, (bt >> 1) & 1);
            comb(m.z, idx.z, az, bm.z, bi.z, (bt >> 2) & 1);
            comb(m.w, idx.w, aw, bm.w, bi.w, (bt >> 3) & 1);
        }
        mfin[tid] = m;                         // empty segment stays NEG_INF (== ref)
        emb4[(size_t)g * 64 + tid] = m;
        if (len <= FLAG_CAP) {
            if (idx.x >= 0) flags[idx.x - start] = 1;
            if (idx.y >= 0) flags[idx.y - start] = 1;
            if (idx.z >= 0) flags[idx.z - start] = 1;
            if (idx.w >= 0) flags[idx.w - start] = 1;
        }
        if (ax | ay | az | aw) sh[3] = 1;      // benign race: all write 1
    }
    __syncthreads();

    const int  tie   = sh[3];
    const bool small = (len <= FLAG_CAP);
    const int  warp  = tid >> 5;
    const int  lane  = tid & 31;

    if (!tie && small) {
        unsigned local = 0;
        for (int i = tid; i < (len + 3) / 4; i += NT) {
            unsigned w = ((unsigned*)flags)[i];
            local += (w * 0x01010101u) >> 24;   // byte-sum of 0/1 flags
        }
        #pragma unroll
        for (int o = 16; o; o >>= 1) local += __shfl_down_sync(0xffffffffu, local, o);
        if (lane == 0 && local) atomicAdd(&sh[2], (int)local);
        __syncthreads();
        const float scale = 1.0f / fmaxf((float)sh[2], 1.0f);
        for (int i = tid; i < len; i += NT)
            attn[start + i] = flags[i] ? scale : 0.0f;
    } else {
        // rare: tie at a column max, or oversized segment -> exact rescan
        if (small) { for (int i = tid; i < FLAG_CAP / 4; i += NT) ((int*)flags)[i] = 0; }
        __syncthreads();
        const float4 ma = mfin[lane];
        const float4 mb = mfin[32 + lane];
        int myCount = 0;
        for (int r = end - 1 - warp; r >= start; r -= 8) {
            float4 a = x4[(size_t)r * 64 + lane];
            float4 b = x4[(size_t)r * 64 + 32 + lane];
            unsigned h = __any_sync(0xffffffffu, f4hit(a, ma) | f4hit(b, mb));
            if (lane == 0) {
                myCount += h ? 1 : 0;
                if (small) flags[r - start] = (unsigned char)(h ? 1 : 0);
                else       attn[r] = h ? 1.0f : 0.0f;
            }
        }
        if (lane == 0 && myCount) atomicAdd(&sh[2], myCount);
        __syncthreads();
        const float scale = 1.0f / fmaxf((float)sh[2], 1.0f);
        if (small) {
            for (int i = tid; i < len; i += NT)
                attn[start + i] = flags[i] ? scale : 0.0f;
        } else {
            for (int i = tid; i < len; i += NT)
                attn[start + i] *= scale;
        }
    }
}

extern "C" void kernel_launch(void* const* d_in, const int* in_sizes, int n_in,
                              void* d_out, int out_size)
{
    const float* x      = (const float*)d_in[0];
    const int*   batchw = (const int*)d_in[1];

    const int N = in_sizes[1];
    const int D = in_sizes[0] / N;
    int G = (out_size - N) / D;                // layout: [emb (G*D) | attn (N)]
    if (G < 1) G = 1;

    float* emb  = (float*)d_out;
    float* attn = emb + (size_t)G * D;

    const size_t smem = 10272 + FLAG_CAP;      // ~18 KB -> 3-4 CTAs/SM
    segmax_argmax_kernel<<<G, NT, smem>>>(
        (const float4*)x, batchw, (float4*)emb, attn, N);
}

// round 9
// speedup vs baseline: 1.7168x; 1.0012x over previous
#include <cuda_runtime.h>

#define NEG_INF   (-3.4e38f)
#define NT        512
#define FLAG_CAP  8192

__device__ __forceinline__ void upd(float v, int r, float& m, int& idx, int& tie) {
    if (v > m)       { m = v; idx = r; tie = 0; }
    else if (v == m) { tie = 1; }
}
// combine b into a (per scalar column). Empty entries have idx < 0.
__device__ __forceinline__ void comb(float& am, int& ai, int& at,
                                     float bm, int bi, int bt) {
    if (bm > am || (bm == am && ai < 0)) { am = bm; ai = bi; at = bt; }
    else if (bm == am && bi >= 0)        { at = 1; }
}
__device__ __forceinline__ bool f4hit(float4 a, float4 m) {
    return (a.x==m.x) | (a.y==m.y) | (a.z==m.z) | (a.w==m.w);
}

// One block per segment, single streaming pass with (max, argmax, tie) per
// scalar column. Hot loop: 8-row fmax tree + one compare per column; exact
// argmax/tie update only when the block max reaches the running max. Ties at
// the final max (rare, ~1e-4/segment) -> exact rescan fallback.
__global__ __launch_bounds__(NT, 2)
void segmax_argmax_kernel(const float4* __restrict__ x4,
                          const int* __restrict__ batchw,   // raw 32-bit words
                          float4* __restrict__ emb4,
                          float* __restrict__ attn,
                          int N)
{
    extern __shared__ unsigned char smem[];
    float4* partM = (float4*)smem;                          // NT*16 = 8192 B
    int4*   partI = (int4*)(smem + 8192);                   // 8192 B
    int*    partT = (int*)(smem + 16384);                   // 2048 B
    float4* mfin  = (float4*)(smem + 18432);                // 1024 B
    int*    sh    = (int*)(smem + 19456);                   //   32 B: 0=start 1=end 2=cnt 3=tie 4=is64
    unsigned char* flags = smem + 19488;                    // FLAG_CAP B

    const int g   = blockIdx.x;
    const int tid = threadIdx.x;

    if (tid == 2) sh[2] = 0;
    if (tid == 3) sh[3] = 0;
    // dtype detect: int64 viewed as 32-bit words -> word[N-1] is a high half == 0.
    if (tid == 4) sh[4] = (N >= 2 && batchw[N - 1] == 0) ? 1 : 0;
    for (int i = tid; i < FLAG_CAP / 4; i += NT) ((int*)flags)[i] = 0;
    __syncthreads();
    const int is64 = sh[4];

    if (tid < 2) {                        // lower_bound(g), lower_bound(g+1)
        int key = g + tid;
        int lo = 0, hi = N;
        while (lo < hi) {
            int mid = (lo + hi) >> 1;
            int v = is64 ? batchw[2 * mid] : batchw[mid];
            if (v < key) lo = mid + 1; else hi = mid;
        }
        sh[tid] = lo;
    }
    __syncthreads();
    const int start = sh[0];
    const int end   = sh[1];
    const int len   = end - start;

    // --- streaming pass ---
    {
        const int q = tid & 63;           // float4 column
        const int s = tid >> 6;           // row subgroup 0..7
        float mx = NEG_INF, my = NEG_INF, mz = NEG_INF, mw = NEG_INF;
        int   ix = -1, iy = -1, iz = -1, iw = -1;
        int   tx = 0,  ty = 0,  tz = 0,  tw = 0;
        int r = start + s;
        const float4* p = x4 + (size_t)r * 64 + q;          // moving base pointer
        for (; r + 56 < end; r += 64, p += 64 * 64) {       // 8 rows/iter, stride 8
            float4 v0 = __ldcs(p);
            float4 v1 = __ldcs(p +  8 * 64);
            float4 v2 = __ldcs(p + 16 * 64);
            float4 v3 = __ldcs(p + 24 * 64);
            float4 v4 = __ldcs(p + 32 * 64);
            float4 v5 = __ldcs(p + 40 * 64);
            float4 v6 = __ldcs(p + 48 * 64);
            float4 v7 = __ldcs(p + 56 * 64);
            float cx = fmaxf(fmaxf(fmaxf(v0.x,v1.x), fmaxf(v2.x,v3.x)),
                             fmaxf(fmaxf(v4.x,v5.x), fmaxf(v6.x,v7.x)));
            float cy = fmaxf(fmaxf(fmaxf(v0.y,v1.y), fmaxf(v2.y,v3.y)),
                             fmaxf(fmaxf(v4.y,v5.y), fmaxf(v6.y,v7.y)));
            float cz = fmaxf(fmaxf(fmaxf(v0.z,v1.z), fmaxf(v2.z,v3.z)),
                             fmaxf(fmaxf(v4.z,v5.z), fmaxf(v6.z,v7.z)));
            float cw = fmaxf(fmaxf(fmaxf(v0.w,v1.w), fmaxf(v2.w,v3.w)),
                             fmaxf(fmaxf(v4.w,v5.w), fmaxf(v6.w,v7.w)));
            if (cx >= mx) {               // rare: exact update in row order
                upd(v0.x, r,    mx, ix, tx); upd(v1.x, r+8,  mx, ix, tx);
                upd(v2.x, r+16, mx, ix, tx); upd(v3.x, r+24, mx, ix, tx);
                upd(v4.x, r+32, mx, ix, tx); upd(v5.x, r+40, mx, ix, tx);
                upd(v6.x, r+48, mx, ix, tx); upd(v7.x, r+56, mx, ix, tx);
            }
            if (cy >= my) {
                upd(v0.y, r,    my, iy, ty); upd(v1.y, r+8,  my, iy, ty);
                upd(v2.y, r+16, my, iy, ty); upd(v3.y, r+24, my, iy, ty);
                upd(v4.y, r+32, my, iy, ty); upd(v5.y, r+40, my, iy, ty);
                upd(v6.y, r+48, my, iy, ty); upd(v7.y, r+56, my, iy, ty);
            }
            if (cz >= mz) {
                upd(v0.z, r,    mz, iz, tz); upd(v1.z, r+8,  mz, iz, tz);
                upd(v2.z, r+16, mz, iz, tz); upd(v3.z, r+24, mz, iz, tz);
                upd(v4.z, r+32, mz, iz, tz); upd(v5.z, r+40, mz, iz, tz);
                upd(v6.z, r+48, mz, iz, tz); upd(v7.z, r+56, mz, iz, tz);
            }
            if (cw >= mw) {
                upd(v0.w, r,    mw, iw, tw); upd(v1.w, r+8,  mw, iw, tw);
                upd(v2.w, r+16, mw, iw, tw); upd(v3.w, r+24, mw, iw, tw);
                upd(v4.w, r+32, mw, iw, tw); upd(v5.w, r+40, mw, iw, tw);
                upd(v6.w, r+48, mw, iw, tw); upd(v7.w, r+56, mw, iw, tw);
            }
        }
        for (; r < end; r += 8, p += 8 * 64) {
            float4 v = __ldcs(p);
            upd(v.x, r, mx, ix, tx); upd(v.y, r, my, iy, ty);
            upd(v.z, r, mz, iz, tz); upd(v.w, r, mw, iw, tw);
        }
        partM[tid] = make_float4(mx, my, mz, mw);
        partI[tid] = make_int4(ix, iy, iz, iw);
        partT[tid] = tx | (ty << 1) | (tz << 2) | (tw << 3);
    }
    __syncthreads();

    // --- reduce 8 subgroups; emit emb, flags, tie ---
    if (tid < 64) {
        float4 m = partM[tid]; int4 idx = partI[tid]; int tb = partT[tid];
        int ax = tb & 1, ay = (tb >> 1) & 1, az = (tb >> 2) & 1, aw = (tb >> 3) & 1;
        #pragma unroll
        for (int k = 1; k < 8; k++) {
            float4 bm = partM[k * 64 + tid];
            int4   bi = partI[k * 64 + tid];
            int    bt = partT[k * 64 + tid];
            comb(m.x, idx.x, ax, bm.x, bi.x,  bt       & 1);
            comb(m.y, idx.y, ay, bm.y, bi.y, (bt >> 1) & 1);
            comb(m.z, idx.z, az, bm.z, bi.z, (bt >> 2) & 1);
            comb(m.w, idx.w, aw, bm.w, bi.w, (bt >> 3) & 1);
        }
        mfin[tid] = m;                         // empty segment stays NEG_INF (== ref)
        emb4[(size_t)g * 64 + tid] = m;
        if (len <= FLAG_CAP) {
            if (idx.x >= 0) flags[idx.x - start] = 1;
            if (idx.y >= 0) flags[idx.y - start] = 1;
            if (idx.z >= 0) flags[idx.z - start] = 1;
            if (idx.w >= 0) flags[idx.w - start] = 1;
        }
        if (ax | ay | az | aw) sh[3] = 1;      // benign race: all write 1
    }
    __syncthreads();

    const int  tie   = sh[3];
    const bool small = (len <= FLAG_CAP);
    const int  warp  = tid >> 5;
    const int  lane  = tid & 31;

    if (!tie && small) {
        unsigned local = 0;
        for (int i = tid; i < (len + 3) / 4; i += NT) {
            unsigned w = ((unsigned*)flags)[i];
            local += (w * 0x01010101u) >> 24;   // byte-sum of 0/1 flags
        }
        #pragma unroll
        for (int o = 16; o; o >>= 1) local += __shfl_down_sync(0xffffffffu, local, o);
        if (lane == 0 && local) atomicAdd(&sh[2], (int)local);
        __syncthreads();
        const float scale = 1.0f / fmaxf((float)sh[2], 1.0f);
        for (int i = tid; i < len; i += NT)
            attn[start + i] = flags[i] ? scale : 0.0f;
    } else {
        // rare: tie at a column max, or oversized segment -> exact rescan
        if (small) { for (int i = tid; i < FLAG_CAP / 4; i += NT) ((int*)flags)[i] = 0; }
        __syncthreads();
        const float4 ma = mfin[lane];
        const float4 mb = mfin[32 + lane];
        int myCount = 0;
        for (int r = end - 1 - warp; r >= start; r -= 16) {
            float4 a = x4[(size_t)r * 64 + lane];
            float4 b = x4[(size_t)r * 64 + 32 + lane];
            unsigned h = __any_sync(0xffffffffu, f4hit(a, ma) | f4hit(b, mb));
            if (lane == 0) {
                myCount += h ? 1 : 0;
                if (small) flags[r - start] = (unsigned char)(h ? 1 : 0);
                else       attn[r] = h ? 1.0f : 0.0f;
            }
        }
        if (lane == 0 && myCount) atomicAdd(&sh[2], myCount);
        __syncthreads();
        const float scale = 1.0f / fmaxf((float)sh[2], 1.0f);
        if (small) {
            for (int i = tid; i < len; i += NT)
                attn[start + i] = flags[i] ? scale : 0.0f;
        } else {
            for (int i = tid; i < len; i += NT)
                attn[start + i] *= scale;
        }
    }
}

extern "C" void kernel_launch(void* const* d_in, const int* in_sizes, int n_in,
                              void* d_out, int out_size)
{
    const float* x      = (const float*)d_in[0];
    const int*   batchw = (const int*)d_in[1];

    const int N = in_sizes[1];
    const int D = in_sizes[0] / N;
    int G = (out_size - N) / D;                // layout: [emb (G*D) | attn (N)]
    if (G < 1) G = 1;

    float* emb  = (float*)d_out;
    float* attn = emb + (size_t)G * D;

    const size_t smem = 19488 + FLAG_CAP;      // ~27 KB -> 2 CTAs/SM at 512 thr
    segmax_argmax_kernel<<<G, NT, smem>>>(
        (const float4*)x, batchw, (float4*)emb, attn, N);
}

// round 10
// speedup vs baseline: 1.7889x; 1.0420x over previous
#include <cuda_runtime.h>

#define NEG_INF (-3.4e38f)

// branchless per-element (max, argmax, tie) update — SELs, no branches
__device__ __forceinline__ void upd(float v, int r, float& m, int& idx, int& tie) {
    bool gt = v > m;
    bool eq = v == m;
    idx = gt ? r : idx;
    tie = gt ? 0 : (eq ? 1 : tie);
    m   = fmaxf(m, v);
}

__device__ __forceinline__ int lower_bound_batch(const int* bw, int N, int key, int is64) {
    int lo = 0, hi = N;
    while (lo < hi) {
        int mid = (lo + hi) >> 1;
        int v = is64 ? bw[2 * mid] : bw[mid];   // int64: low word == value
        if (v < key) lo = mid + 1; else hi = mid;
    }
    return lo;
}

// K1: one CTA per (segment, column-half). Thread owns ONE scalar column:
// streams its column over the segment rows with branchless (max,argmax,tie),
// writes emb, and marks matched rows with attn[row] = 1.0f.
// 128 threads x <=32 regs -> 16 CTAs/SM (100% occupancy).
__global__ __launch_bounds__(128, 16)
void segmax_mark_kernel(const float* __restrict__ x,
                        const int* __restrict__ batchw,
                        float* __restrict__ emb,
                        float* __restrict__ attn,
                        int N)
{
    __shared__ int sh[4];                     // 0=start 1=end 2=is64
    const int g    = blockIdx.x >> 1;
    const int half = blockIdx.x & 1;
    const int tid  = threadIdx.x;
    const int col  = half * 128 + tid;

    // dtype detect: int64 viewed as 32-bit words -> word[N-1] is a high half == 0.
    if (tid == 2) sh[2] = (N >= 2 && batchw[N - 1] == 0) ? 1 : 0;
    __syncthreads();
    const int is64 = sh[2];
    if (tid < 2) sh[tid] = lower_bound_batch(batchw, N, g + tid, is64);
    __syncthreads();
    const int start = sh[0];
    const int end   = sh[1];

    float m = NEG_INF; int idx = -1; int tie = 0;
    {
        const float* p = x + (size_t)start * 256 + col;
        int r = start;
        for (; r + 7 < end; r += 8, p += 8 * 256) {   // MLP=8 independent loads
            float v0 = __ldcs(p);
            float v1 = __ldcs(p + 1 * 256);
            float v2 = __ldcs(p + 2 * 256);
            float v3 = __ldcs(p + 3 * 256);
            float v4 = __ldcs(p + 4 * 256);
            float v5 = __ldcs(p + 5 * 256);
            float v6 = __ldcs(p + 6 * 256);
            float v7 = __ldcs(p + 7 * 256);
            upd(v0, r,   m, idx, tie); upd(v1, r+1, m, idx, tie);
            upd(v2, r+2, m, idx, tie); upd(v3, r+3, m, idx, tie);
            upd(v4, r+4, m, idx, tie); upd(v5, r+5, m, idx, tie);
            upd(v6, r+6, m, idx, tie); upd(v7, r+7, m, idx, tie);
        }
        for (; r < end; r++, p += 256)
            upd(__ldcs(p), r, m, idx, tie);
    }

    emb[(size_t)g * 256 + col] = m;           // empty segment stays NEG_INF (== ref)

    if (!tie && idx >= 0) attn[idx] = 1.0f;   // mark matched row (idempotent)

    // rare: exact-bit tie at the column max -> warp-cooperative column rescan
    unsigned tmask = __ballot_sync(0xffffffffu, (tie != 0) && (idx >= 0));
    const int lane = tid & 31;
    while (tmask) {
        int L = __ffs(tmask) - 1; tmask &= tmask - 1;
        float mv   = __shfl_sync(0xffffffffu, m,   L);
        int   colL = __shfl_sync(0xffffffffu, col, L);
        for (int rr = start + lane; rr < end; rr += 32)
            if (x[(size_t)rr * 256 + colL] == mv) attn[rr] = 1.0f;
    }
}

// K2: per segment, count rows marked 1.0f, then attn = mark ? 1/max(cnt,1) : 0.
// Replay-safe: matches are deterministic; stale values are 0 or scale != 1.0f.
__global__ __launch_bounds__(256)
void normalize_kernel(const int* __restrict__ batchw,
                      float* __restrict__ attn,
                      int N)
{
    __shared__ int sh[4];                     // 0=start 1=end 2=count 3=is64
    const int g   = blockIdx.x;
    const int tid = threadIdx.x;

    if (tid == 2) sh[2] = 0;
    if (tid == 3) sh[3] = (N >= 2 && batchw[N - 1] == 0) ? 1 : 0;
    __syncthreads();
    const int is64 = sh[3];
    if (tid < 2) sh[tid] = lower_bound_batch(batchw, N, g + tid, is64);
    __syncthreads();
    const int start = sh[0];
    const int end   = sh[1];

    int local = 0;
    for (int i = start + tid; i < end; i += 256)
        local += (attn[i] == 1.0f) ? 1 : 0;
    #pragma unroll
    for (int o = 16; o; o >>= 1) local += __shfl_down_sync(0xffffffffu, local, o);
    if ((tid & 31) == 0 && local) atomicAdd(&sh[2], local);
    __syncthreads();

    const float scale = 1.0f / fmaxf((float)sh[2], 1.0f);
    for (int i = start + tid; i < end; i += 256) {
        float v = attn[i];                    // L2-hot re-read
        attn[i] = (v == 1.0f) ? scale : 0.0f;
    }
}

extern "C" void kernel_launch(void* const* d_in, const int* in_sizes, int n_in,
                              void* d_out, int out_size)
{
    const float* x      = (const float*)d_in[0];
    const int*   batchw = (const int*)d_in[1];

    const int N = in_sizes[1];
    const int D = in_sizes[0] / N;
    int G = (out_size - N) / D;               // layout: [emb (G*D) | attn (N)]
    if (G < 1) G = 1;

    float* emb  = (float*)d_out;
    float* attn = emb + (size_t)G * D;

    segmax_mark_kernel<<<2 * G, 128>>>(x, batchw, emb, attn, N);
    normalize_kernel<<<G, 256>>>(batchw, attn, N);
}

// round 11
// speedup vs baseline: 1.8676x; 1.0440x over previous
#include <cuda_runtime.h>

#define NEG_INF (-3.4e38f)
#define MAXG    65536

__device__ int g_bounds[MAXG + 1];   // segment row bounds, published by K1

// branchless per-element (max, argmax, tie) update — SELs, no branches
__device__ __forceinline__ void upd(float v, int r, float& m, int& idx, int& tie) {
    bool gt = v > m;
    bool eq = v == m;
    idx = gt ? r : idx;
    tie = gt ? 0 : (eq ? 1 : tie);
    m   = fmaxf(m, v);
}
// merge accumulator b into a; empty entries have idx < 0
__device__ __forceinline__ void comb(float& am, int& ai, int& at,
                                     float bm, int bi, int bt) {
    if (bm > am || (bm == am && ai < 0)) { am = bm; ai = bi; at = bt; }
    else if (bm == am && bi >= 0)        { at = 1; }
}

__device__ __forceinline__ int lower_bound_batch(const int* bw, int N, int key, int is64) {
    int lo = 0, hi = N;
    while (lo < hi) {
        int mid = (lo + hi) >> 1;
        int v = is64 ? bw[2 * mid] : bw[mid];   // int64: low word == value
        if (v < key) lo = mid + 1; else hi = mid;
    }
    return lo;
}

// K1: one CTA per (segment, column-half); thread owns ONE scalar column.
// Streams the column with branchless dual-accumulator (max, argmax, tie),
// writes emb, marks matched rows attn[row]=1.0f, publishes bounds for K2.
__global__ __launch_bounds__(128, 16)
void segmax_mark_kernel(const float* __restrict__ x,
                        const int* __restrict__ batchw,
                        float* __restrict__ emb,
                        float* __restrict__ attn,
                        int N, int G)
{
    __shared__ int sh[4];                     // 0=start 1=end 2=is64
    const int g    = blockIdx.x >> 1;
    const int half = blockIdx.x & 1;
    const int tid  = threadIdx.x;
    const int col  = half * 128 + tid;

    // dtype detect: int64 viewed as 32-bit words -> word[N-1] is a high half == 0.
    if (tid == 2) sh[2] = (N >= 2 && batchw[N - 1] == 0) ? 1 : 0;
    __syncthreads();
    const int is64 = sh[2];
    if (tid < 2) sh[tid] = lower_bound_batch(batchw, N, g + tid, is64);
    __syncthreads();
    const int start = sh[0];
    const int end   = sh[1];

    if (half == 0 && tid == 0) {              // publish bounds for K2
        g_bounds[g] = start;
        if (g == G - 1) g_bounds[G] = end;
    }

    float m0 = NEG_INF, m1 = NEG_INF;
    int   i0 = -1, i1 = -1, t0 = 0, t1 = 0;
    {
        const float* p = x + (size_t)start * 256 + col;
        int r = start;
        for (; r + 7 < end; r += 8, p += 8 * 256) {   // MLP=8 independent loads
            float v0 = __ldcs(p);
            float v1 = __ldcs(p + 1 * 256);
            float v2 = __ldcs(p + 2 * 256);
            float v3 = __ldcs(p + 3 * 256);
            float v4 = __ldcs(p + 4 * 256);
            float v5 = __ldcs(p + 5 * 256);
            float v6 = __ldcs(p + 6 * 256);
            float v7 = __ldcs(p + 7 * 256);
            upd(v0, r,   m0, i0, t0); upd(v1, r+1, m1, i1, t1);  // two chains
            upd(v2, r+2, m0, i0, t0); upd(v3, r+3, m1, i1, t1);
            upd(v4, r+4, m0, i0, t0); upd(v5, r+5, m1, i1, t1);
            upd(v6, r+6, m0, i0, t0); upd(v7, r+7, m1, i1, t1);
        }
        for (; r < end; r++, p += 256)
            upd(__ldcs(p), r, m0, i0, t0);
    }
    comb(m0, i0, t0, m1, i1, t1);             // exact tie-aware merge

    emb[(size_t)g * 256 + col] = m0;          // empty segment stays NEG_INF (== ref)

    if (!t0 && i0 >= 0) attn[i0] = 1.0f;      // mark matched row (idempotent)

    // rare: exact-bit tie at the column max -> warp-cooperative column rescan
    unsigned tmask = __ballot_sync(0xffffffffu, (t0 != 0) && (i0 >= 0));
    const int lane = tid & 31;
    while (tmask) {
        int L = __ffs(tmask) - 1; tmask &= tmask - 1;
        float mv   = __shfl_sync(0xffffffffu, m0,  L);
        int   colL = __shfl_sync(0xffffffffu, col, L);
        for (int rr = start + lane; rr < end; rr += 32)
            if (x[(size_t)rr * 256 + colL] == mv) attn[rr] = 1.0f;
    }
}

// K2: per segment, count rows marked 1.0f, rewrite attn = mark ? 1/max(cnt,1) : 0.
// Bounds precomputed by K1 (no binary search); values register-cached (1 read pass).
// Replay-safe: marks are deterministic; stale values are 0 or scale != 1.0f.
__global__ __launch_bounds__(256)
void normalize_kernel(float* __restrict__ attn)
{
    __shared__ int scount;
    const int g   = blockIdx.x;
    const int tid = threadIdx.x;
    if (tid == 0) scount = 0;
    __syncthreads();

    const int start = g_bounds[g];
    const int end   = g_bounds[g + 1];
    const int len   = end - start;

    if (len <= 8 * 256) {                     // register-cached fast path (always, in practice)
        float vals[8];
        int   local = 0, k = 0;
        for (int i = start + tid; i < end; i += 256, k++) {
            vals[k] = attn[i];
            local += (vals[k] == 1.0f) ? 1 : 0;
        }
        #pragma unroll
        for (int o = 16; o; o >>= 1) local += __shfl_down_sync(0xffffffffu, local, o);
        if ((tid & 31) == 0 && local) atomicAdd(&scount, local);
        __syncthreads();
        const float scale = 1.0f / fmaxf((float)scount, 1.0f);
        k = 0;
        for (int i = start + tid; i < end; i += 256, k++)
            attn[i] = (vals[k] == 1.0f) ? scale : 0.0f;
    } else {                                   // oversized segment fallback
        int local = 0;
        for (int i = start + tid; i < end; i += 256)
            local += (attn[i] == 1.0f) ? 1 : 0;
        #pragma unroll
        for (int o = 16; o; o >>= 1) local += __shfl_down_sync(0xffffffffu, local, o);
        if ((tid & 31) == 0 && local) atomicAdd(&scount, local);
        __syncthreads();
        const float scale = 1.0f / fmaxf((float)scount, 1.0f);
        for (int i = start + tid; i < end; i += 256) {
            float v = attn[i];
            attn[i] = (v == 1.0f) ? scale : 0.0f;
        }
    }
}

extern "C" void kernel_launch(void* const* d_in, const int* in_sizes, int n_in,
                              void* d_out, int out_size)
{
    const float* x      = (const float*)d_in[0];
    const int*   batchw = (const int*)d_in[1];

    const int N = in_sizes[1];
    const int D = in_sizes[0] / N;
    int G = (out_size - N) / D;               // layout: [emb (G*D) | attn (N)]
    if (G < 1) G = 1;
    if (G > MAXG) G = MAXG;                   // defensive; never expected

    float* emb  = (float*)d_out;
    float* attn = emb + (size_t)G * D;

    segmax_mark_kernel<<<2 * G, 128>>>(x, batchw, emb, attn, N, G);
    normalize_kernel<<<G, 256>>>(attn);
}

// round 12
// speedup vs baseline: 1.8896x; 1.0118x over previous
#include <cuda_runtime.h>

#define NEG_INF (-3.4e38f)
#define MAXG    65536

__device__ int g_bounds[MAXG + 1];   // segment row bounds, published by K1

// branchless per-element (max, argmax, tie) update — SELs, no branches
__device__ __forceinline__ void upd(float v, int r, float& m, int& idx, int& tie) {
    bool gt = v > m;
    bool eq = v == m;
    idx = gt ? r : idx;
    tie = gt ? 0 : (eq ? 1 : tie);
    m   = fmaxf(m, v);
}

__device__ __forceinline__ int lower_bound_batch(const int* bw, int N, int key, int is64) {
    int lo = 0, hi = N;
    while (lo < hi) {
        int mid = (lo + hi) >> 1;
        int v = is64 ? bw[2 * mid] : bw[mid];   // int64: low word == value
        if (v < key) lo = mid + 1; else hi = mid;
    }
    return lo;
}

// K1: one CTA per segment; thread owns ONE scalar column (col = tid), so the
// CTA streams its segment fully contiguously (whole 1KB rows). Branchless
// (max, argmax, tie); marks matched rows attn[row]=1.0f; publishes bounds.
// 256 thr x 8 CTAs/SM = 2048 thr/SM (100% occupancy), regs capped at 32.
__global__ __launch_bounds__(256, 8)
void segmax_mark_kernel(const float* __restrict__ x,
                        const int* __restrict__ batchw,
                        float* __restrict__ emb,
                        float* __restrict__ attn,
                        int N, int G)
{
    __shared__ int sh[4];                     // 0=start 1=end 2=is64
    const int g   = blockIdx.x;
    const int tid = threadIdx.x;
    const int col = tid;                      // scalar column 0..255

    // dtype detect: int64 viewed as 32-bit words -> word[N-1] is a high half == 0.
    if (tid == 2) sh[2] = (N >= 2 && batchw[N - 1] == 0) ? 1 : 0;
    __syncthreads();
    const int is64 = sh[2];
    if (tid < 2) sh[tid] = lower_bound_batch(batchw, N, g + tid, is64);
    __syncthreads();
    const int start = sh[0];
    const int end   = sh[1];

    if (tid == 0) {                           // publish bounds for K2
        g_bounds[g] = start;
        if (g == G - 1) g_bounds[G] = end;
    }

    float m = NEG_INF; int idx = -1; int tie = 0;
    {
        const float* p = x + (size_t)start * 256 + col;
        int r = start;
        for (; r + 7 < end; r += 8, p += 8 * 256) {   // MLP=8 independent loads
            float v0 = __ldcs(p);
            float v1 = __ldcs(p + 1 * 256);
            float v2 = __ldcs(p + 2 * 256);
            float v3 = __ldcs(p + 3 * 256);
            float v4 = __ldcs(p + 4 * 256);
            float v5 = __ldcs(p + 5 * 256);
            float v6 = __ldcs(p + 6 * 256);
            float v7 = __ldcs(p + 7 * 256);
            upd(v0, r,   m, idx, tie); upd(v1, r+1, m, idx, tie);
            upd(v2, r+2, m, idx, tie); upd(v3, r+3, m, idx, tie);
            upd(v4, r+4, m, idx, tie); upd(v5, r+5, m, idx, tie);
            upd(v6, r+6, m, idx, tie); upd(v7, r+7, m, idx, tie);
        }
        for (; r < end; r++, p += 256)
            upd(__ldcs(p), r, m, idx, tie);
    }

    emb[(size_t)g * 256 + col] = m;           // empty segment stays NEG_INF (== ref)

    if (!tie && idx >= 0) attn[idx] = 1.0f;   // mark matched row (idempotent)

    // rare: exact-bit tie at the column max -> warp-cooperative column rescan
    unsigned tmask = __ballot_sync(0xffffffffu, (tie != 0) && (idx >= 0));
    const int lane = tid & 31;
    while (tmask) {
        int L = __ffs(tmask) - 1; tmask &= tmask - 1;
        float mv   = __shfl_sync(0xffffffffu, m,   L);
        int   colL = __shfl_sync(0xffffffffu, col, L);
        for (int rr = start + lane; rr < end; rr += 32)
            if (x[(size_t)rr * 256 + colL] == mv) attn[rr] = 1.0f;
    }
}

// K2: per segment, count rows marked 1.0f, rewrite attn = mark ? 1/max(cnt,1) : 0.
// Bounds precomputed by K1 (no binary search); values register-cached (1 read pass).
// Replay-safe: marks are deterministic; stale values are 0 or scale != 1.0f.
__global__ __launch_bounds__(256)
void normalize_kernel(float* __restrict__ attn)
{
    __shared__ int scount;
    const int g   = blockIdx.x;
    const int tid = threadIdx.x;
    if (tid == 0) scount = 0;
    __syncthreads();

    const int start = g_bounds[g];
    const int end   = g_bounds[g + 1];
    const int len   = end - start;

    if (len <= 8 * 256) {                     // register-cached fast path (always, in practice)
        float vals[8];
        int   local = 0, k = 0;
        for (int i = start + tid; i < end; i += 256, k++) {
            vals[k] = attn[i];
            local += (vals[k] == 1.0f) ? 1 : 0;
        }
        #pragma unroll
        for (int o = 16; o; o >>= 1) local += __shfl_down_sync(0xffffffffu, local, o);
        if ((tid & 31) == 0 && local) atomicAdd(&scount, local);
        __syncthreads();
        const float scale = 1.0f / fmaxf((float)scount, 1.0f);
        k = 0;
        for (int i = start + tid; i < end; i += 256, k++)
            attn[i] = (vals[k] == 1.0f) ? scale : 0.0f;
    } else {                                   // oversized segment fallback
        int local = 0;
        for (int i = start + tid; i < end; i += 256)
            local += (attn[i] == 1.0f) ? 1 : 0;
        #pragma unroll
        for (int o = 16; o; o >>= 1) local += __shfl_down_sync(0xffffffffu, local, o);
        if ((tid & 31) == 0 && local) atomicAdd(&scount, local);
        __syncthreads();
        const float scale = 1.0f / fmaxf((float)scount, 1.0f);
        for (int i = start + tid; i < end; i += 256) {
            float v = attn[i];
            attn[i] = (v == 1.0f) ? scale : 0.0f;
        }
    }
}

extern "C" void kernel_launch(void* const* d_in, const int* in_sizes, int n_in,
                              void* d_out, int out_size)
{
    const float* x      = (const float*)d_in[0];
    const int*   batchw = (const int*)d_in[1];

    const int N = in_sizes[1];
    const int D = in_sizes[0] / N;
    int G = (out_size - N) / D;               // layout: [emb (G*D) | attn (N)]
    if (G < 1) G = 1;
    if (G > MAXG) G = MAXG;                   // defensive; never expected

    float* emb  = (float*)d_out;
    float* attn = emb + (size_t)G * D;

    segmax_mark_kernel<<<G, 256>>>(x, batchw, emb, attn, N, G);
    normalize_kernel<<<G, 256>>>(attn);
}